// round 12
// baseline (speedup 1.0000x reference)
#include <cuda_runtime.h>
#include <cuda_fp16.h>
#include <cstdint>

#define N_NODES 8192
#define F_DIM   256
#define K_KEEP  4096
#define KDIM    8192
#define NKC     (KDIM / 64)        // 128 k-chunks of 64 fp16
#define TILE_BYTES 32768           // 256 rows x 128 bytes (pre-swizzled)
#define STAGES  3
#define STAGE_BYTES 32768          // A 16KB + B 16KB (128 rows each)

// ---------------- scratch (__device__ globals) ------------------------------
__device__ float          g_y[N_NODES];
__device__ unsigned char  g_keep[N_NODES];
__device__ int            g_idx[K_KEEP];
__device__ int            g_pos[N_NODES];
__device__ __align__(16) char g_Atiles[(size_t)16 * NKC * TILE_BYTES];
__device__ __align__(16) char g_Btiles[(size_t)16 * NKC * TILE_BYTES];

// ---------------- PTX helpers ------------------------------------------------
__device__ __forceinline__ uint32_t smem_u32(const void* p) {
    return (uint32_t)__cvta_generic_to_shared(p);
}
__device__ __forceinline__ void cp_async16(uint32_t saddr, const void* gaddr) {
    asm volatile("cp.async.cg.shared.global [%0], [%1], 16;\n" :: "r"(saddr), "l"(gaddr));
}
__device__ __forceinline__ void cp_commit() {
    asm volatile("cp.async.commit_group;\n" ::);
}
__device__ __forceinline__ void ldsm4(uint32_t& r0, uint32_t& r1, uint32_t& r2, uint32_t& r3,
                                      uint32_t addr) {
    asm volatile("ldmatrix.sync.aligned.m8n8.x4.shared.b16 {%0,%1,%2,%3}, [%4];\n"
                 : "=r"(r0), "=r"(r1), "=r"(r2), "=r"(r3) : "r"(addr));
}
// fp16 x fp16 -> fp16 accumulate (the potential double-rate legacy path)
__device__ __forceinline__ void mma16816_f16(uint32_t* d, const uint32_t* a, const uint32_t* b) {
    asm volatile("mma.sync.aligned.m16n8k16.row.col.f16.f16.f16.f16 "
                 "{%0,%1}, {%2,%3,%4,%5}, {%6,%7}, {%0,%1};\n"
                 : "+r"(d[0]), "+r"(d[1])
                 : "r"(a[0]), "r"(a[1]), "r"(a[2]), "r"(a[3]), "r"(b[0]), "r"(b[1]));
}
__device__ __forceinline__ uint32_t swz(uint32_t off) { return off ^ ((off >> 3) & 0x70); }

// ---------------- 1. y = (X @ p) * rsqrt(sum(p^2)) --------------------------
__global__ void compute_y_kernel(const float* __restrict__ X, const float* __restrict__ p) {
    __shared__ float sp[F_DIM];
    __shared__ float red[8];
    int t = threadIdx.x;
    sp[t] = p[t];
    __syncthreads();
    float v = sp[t] * sp[t];
    #pragma unroll
    for (int o = 16; o; o >>= 1) v += __shfl_xor_sync(0xffffffffu, v, o);
    if ((t & 31) == 0) red[t >> 5] = v;
    __syncthreads();
    float sumsq = 0.f;
    #pragma unroll
    for (int w = 0; w < 8; ++w) sumsq += red[w];
    float inv = rsqrtf(sumsq);

    int wid = t >> 5, lane = t & 31;
    int row = blockIdx.x * 8 + wid;
    const float* xr = X + (size_t)row * F_DIM;
    float acc = 0.f;
    #pragma unroll
    for (int u = 0; u < 8; ++u) acc += xr[lane + 32 * u] * sp[lane + 32 * u];
    #pragma unroll
    for (int o = 16; o; o >>= 1) acc += __shfl_xor_sync(0xffffffffu, acc, o);
    if (lane == 0) g_y[row] = acc * inv;
}

// ---------------- 2. rank-based top-k (2 threads per node) -------------------
__global__ void rank_kernel() {
    __shared__ float sy[N_NODES];
    __shared__ int sc[256];
    int t = threadIdx.x;
    for (int j = t; j < N_NODES; j += 256) sy[j] = g_y[j];
    __syncthreads();
    int half = t >> 7;
    int i = blockIdx.x * 128 + (t & 127);
    float yi = sy[i];
    int cnt = 0;
    int j0 = half * (N_NODES / 2);
    #pragma unroll 16
    for (int jj = 0; jj < N_NODES / 2; ++jj) {
        int j = j0 + jj;
        float v = sy[j];
        cnt += (int)((v > yi) || (v == yi && j < i));
    }
    sc[t] = cnt;
    __syncthreads();
    if (half == 0) {
        int total = cnt + sc[t + 128];
        g_keep[i] = (total < K_KEEP) ? 1 : 0;
    }
}

// ---------------- 3. compact -> idx / pos ------------------------------------
__global__ void compact_kernel() {
    __shared__ int s[1024];
    int t = threadIdx.x;
    int base = t * 8;
    int flags[8];
    int c = 0;
    #pragma unroll
    for (int u = 0; u < 8; ++u) { flags[u] = g_keep[base + u]; c += flags[u]; }
    s[t] = c;
    __syncthreads();
    for (int off = 1; off < 1024; off <<= 1) {
        int add = (t >= off) ? s[t - off] : 0;
        __syncthreads();
        s[t] += add;
        __syncthreads();
    }
    int pos = s[t] - c;
    #pragma unroll
    for (int u = 0; u < 8; ++u) {
        int i = base + u;
        if (flags[u]) { g_idx[pos] = i; g_pos[i] = pos; ++pos; }
        else          { g_pos[i] = -1; }
    }
}

// ---------------- 4. X_pooled (float4, 2 per thread) -------------------------
__global__ void xpool_kernel(const float* __restrict__ X, float* __restrict__ outX) {
    int r = blockIdx.x * 8 + (threadIdx.x >> 5);
    int lane = threadIdx.x & 31;
    int i = g_idx[r];
    float g = tanhf(g_y[i]);
    const float4* src = (const float4*)(X + (size_t)i * F_DIM);
    float4* dst = (float4*)(outX + (size_t)r * F_DIM);
    #pragma unroll
    for (int u = 0; u < 2; ++u) {
        float4 v = src[lane + 32 * u];
        v.x *= g; v.y *= g; v.z *= g; v.w *= g;
        dst[lane + 32 * u] = v;
    }
}

// ---------------- 5. fused gather (float4 fill; fp16 operands) ---------------
__global__ void gather_kernel(const float* __restrict__ A) {
    __shared__ float tile[64][65];
    int R0 = blockIdx.x * 64;
    int C0 = blockIdx.y * 64;
    int t = threadIdx.x;
    #pragma unroll
    for (int i = 0; i < 4; ++i) {
        int lin = t + 256 * i;
        int r = lin >> 4, c4 = lin & 15;
        float4 v = *(const float4*)(A + (size_t)(R0 + r) * N_NODES + C0 + c4 * 4);
        tile[r][c4 * 4 + 0] = v.x;
        tile[r][c4 * 4 + 1] = v.y;
        tile[r][c4 * 4 + 2] = v.z;
        tile[r][c4 * 4 + 3] = v.w;
    }
    __syncthreads();

    int kcA = C0 >> 6;
    int kcB = R0 >> 6;
    #pragma unroll
    for (int i = 0; i < 8; ++i) {
        int lin = t + 256 * i;
        int r = lin >> 5, c2 = lin & 31;
        int p = g_pos[R0 + r];
        if (p >= 0) {
            __half2 v = __floats2half2_rn(tile[r][2 * c2], tile[r][2 * c2 + 1]);
            size_t base = (((size_t)(p >> 8)) * NKC + kcA) << 15;
            uint32_t off = swz((uint32_t)(p & 255) * 128 + c2 * 4);
            *(__half2*)(g_Atiles + base + off) = v;
        }
    }
    #pragma unroll
    for (int i = 0; i < 8; ++i) {
        int lin = t + 256 * i;
        int c = lin >> 5, r2 = lin & 31;
        int q = g_pos[C0 + c];
        if (q >= 0) {
            __half2 v = __floats2half2_rn(tile[2 * r2][c], tile[2 * r2 + 1][c]);
            size_t base = (((size_t)(q >> 8)) * NKC + kcB) << 15;
            uint32_t off = swz((uint32_t)(q & 255) * 128 + r2 * 4);
            *(__half2*)(g_Btiles + base + off) = v;
        }
    }
}

// ---------------- 6. HMMA GEMM, f16-accumulate per k-chunk -------------------
// BM=BN=128, BK=64, 8 warps (2x4), warp tile 64x32, 3-stage cp.async,
// one sync per k-iter, 2 CTAs/SM. f16 chunk accum (k<=64) -> f32 promote.
__global__ void __launch_bounds__(256, 2) gemm_hmma_kernel(float* __restrict__ C) {
    extern __shared__ char smem_raw[];
    const int t = threadIdx.x;
    const int lane = t & 31, wid = t >> 5;
    const int wm = wid >> 2, wn = wid & 3;
    const int bm = blockIdx.y, bn = blockIdx.x;

    const char* Ag = g_Atiles + (((size_t)(bm >> 1)) * NKC) * TILE_BYTES + (size_t)(bm & 1) * 16384;
    const char* Bg = g_Btiles + (((size_t)(bn >> 1)) * NKC) * TILE_BYTES + (size_t)(bn & 1) * 16384;

    uint32_t sbase = (smem_u32(smem_raw) + 1023) & ~1023u;

    auto issue = [&](int kt) {
        uint32_t sA = sbase + (kt % STAGES) * STAGE_BYTES;
        const char* ga = Ag + (size_t)kt * TILE_BYTES;
        const char* gb = Bg + (size_t)kt * TILE_BYTES;
        #pragma unroll
        for (int i = 0; i < 4; ++i)
            cp_async16(sA + (t + 256 * i) * 16, ga + (size_t)(t + 256 * i) * 16);
        #pragma unroll
        for (int i = 0; i < 4; ++i)
            cp_async16(sA + 16384 + (t + 256 * i) * 16, gb + (size_t)(t + 256 * i) * 16);
        cp_commit();
    };

    float c[4][4][4] = {};

    issue(0); issue(1);
    for (int kt = 0; kt < NKC; ++kt) {
        if (kt < NKC - 1) asm volatile("cp.async.wait_group 1;\n" ::);
        else              asm volatile("cp.async.wait_group 0;\n" ::);
        __syncthreads();
        if (kt + 2 < NKC) issue(kt + 2);

        uint32_t sA = sbase + (kt % STAGES) * STAGE_BYTES;
        uint32_t sB = sA + 16384;

        uint32_t ch[4][4][2] = {};              // f16 chunk accumulators (zeroed)
        #pragma unroll
        for (int ks = 0; ks < 4; ++ks) {
            uint32_t a[4][4], b[4][2];
            #pragma unroll
            for (int mt = 0; mt < 4; ++mt) {
                int row = wm * 64 + mt * 16 + (lane & 15);
                int chunk = (ks * 2 + (lane >> 4)) ^ (row & 7);
                ldsm4(a[mt][0], a[mt][1], a[mt][2], a[mt][3], sA + row * 128 + chunk * 16);
            }
            #pragma unroll
            for (int pr = 0; pr < 2; ++pr) {
                int row = wn * 32 + pr * 16 + ((lane >> 4) & 1) * 8 + (lane & 7);
                int chunk = (ks * 2 + ((lane >> 3) & 1)) ^ (row & 7);
                ldsm4(b[pr * 2][0], b[pr * 2][1], b[pr * 2 + 1][0], b[pr * 2 + 1][1],
                      sB + row * 128 + chunk * 16);
            }
            #pragma unroll
            for (int mt = 0; mt < 4; ++mt)
                #pragma unroll
                for (int nt = 0; nt < 4; ++nt)
                    mma16816_f16(ch[mt][nt], a[mt], b[nt]);
        }
        // promote f16 chunk sums into persistent f32 accumulators
        #pragma unroll
        for (int mt = 0; mt < 4; ++mt)
            #pragma unroll
            for (int nt = 0; nt < 4; ++nt) {
                float2 lo = __half22float2(*(__half2*)&ch[mt][nt][0]);
                float2 hi = __half22float2(*(__half2*)&ch[mt][nt][1]);
                c[mt][nt][0] += lo.x; c[mt][nt][1] += lo.y;
                c[mt][nt][2] += hi.x; c[mt][nt][3] += hi.y;
            }
    }
    __syncthreads();

    // epilogue: streaming stores (C is write-once)
    int groupId = lane >> 2, tid4 = lane & 3;
    #pragma unroll
    for (int mt = 0; mt < 4; ++mt) {
        size_t row0 = (size_t)bm * 128 + wm * 64 + mt * 16 + groupId;
        #pragma unroll
        for (int nt = 0; nt < 4; ++nt) {
            size_t col = (size_t)bn * 128 + wn * 32 + nt * 8 + tid4 * 2;
            __stcs((float2*)(C + row0 * K_KEEP + col),
                   make_float2(c[mt][nt][0], c[mt][nt][1]));
            __stcs((float2*)(C + (row0 + 8) * K_KEEP + col),
                   make_float2(c[mt][nt][2], c[mt][nt][3]));
        }
    }
}

// ---------------- launch ------------------------------------------------------
extern "C" void kernel_launch(void* const* d_in, const int* in_sizes, int n_in,
                              void* d_out, int out_size) {
    const float* X = (const float*)d_in[0];   // (8192, 256)
    const float* A = (const float*)d_in[1];   // (8192, 8192)
    const float* p = (const float*)d_in[2];   // (256, 1)

    float* out  = (float*)d_out;
    float* outX = out;                              // (4096, 256)
    float* outA = out + (size_t)K_KEEP * F_DIM;     // (4096, 4096)

    compute_y_kernel<<<N_NODES / 8, 256>>>(X, p);
    rank_kernel<<<N_NODES / 128, 256>>>();
    compact_kernel<<<1, 1024>>>();
    xpool_kernel<<<K_KEEP / 8, 256>>>(X, outX);
    gather_kernel<<<dim3(N_NODES / 64, N_NODES / 64), 256>>>(A);

    const int smem_bytes = STAGES * STAGE_BYTES + 1024;   // 99328 -> 2 CTAs/SM
    cudaFuncSetAttribute(gemm_hmma_kernel, cudaFuncAttributeMaxDynamicSharedMemorySize, smem_bytes);
    gemm_hmma_kernel<<<dim3(K_KEEP / 128, K_KEEP / 128), 256, smem_bytes>>>(outA);
}

// round 13
// speedup vs baseline: 1.2490x; 1.2490x over previous
#include <cuda_runtime.h>
#include <cuda_fp16.h>
#include <cstdint>

#define N_NODES 8192
#define F_DIM   256
#define K_KEEP  4096
#define KDIM    8192
#define NKC     (KDIM / 64)        // 128 k-chunks of 64 fp16
#define TILE_BYTES 32768           // 256 rows x 128 bytes (pre-swizzled)
#define STAGES  3
#define STAGE_BYTES 32768          // A 16KB + B 16KB (128 rows each)

// ---------------- scratch (__device__ globals) ------------------------------
__device__ float          g_y[N_NODES];
__device__ unsigned char  g_keep[N_NODES];
__device__ int            g_idx[K_KEEP];
__device__ int            g_pos[N_NODES];
__device__ __align__(16) char g_Atiles[(size_t)16 * NKC * TILE_BYTES];
__device__ __align__(16) char g_Btiles[(size_t)16 * NKC * TILE_BYTES];

// ---------------- PTX helpers ------------------------------------------------
__device__ __forceinline__ uint32_t smem_u32(const void* p) {
    return (uint32_t)__cvta_generic_to_shared(p);
}
__device__ __forceinline__ void cp_async16(uint32_t saddr, const void* gaddr) {
    asm volatile("cp.async.cg.shared.global [%0], [%1], 16;\n" :: "r"(saddr), "l"(gaddr));
}
__device__ __forceinline__ void cp_commit() {
    asm volatile("cp.async.commit_group;\n" ::);
}
__device__ __forceinline__ void ldsm4(uint32_t& r0, uint32_t& r1, uint32_t& r2, uint32_t& r3,
                                      uint32_t addr) {
    asm volatile("ldmatrix.sync.aligned.m8n8.x4.shared.b16 {%0,%1,%2,%3}, [%4];\n"
                 : "=r"(r0), "=r"(r1), "=r"(r2), "=r"(r3) : "r"(addr));
}
// fp16 x fp16 -> f32 accumulate
__device__ __forceinline__ void mma16816(float* c, const uint32_t* a, const uint32_t* b) {
    asm volatile("mma.sync.aligned.m16n8k16.row.col.f32.f16.f16.f32 "
                 "{%0,%1,%2,%3}, {%4,%5,%6,%7}, {%8,%9}, {%0,%1,%2,%3};\n"
                 : "+f"(c[0]), "+f"(c[1]), "+f"(c[2]), "+f"(c[3])
                 : "r"(a[0]), "r"(a[1]), "r"(a[2]), "r"(a[3]), "r"(b[0]), "r"(b[1]));
}
__device__ __forceinline__ uint32_t swz(uint32_t off) { return off ^ ((off >> 3) & 0x70); }

// ---------------- 1. y = (X @ p) * rsqrt(sum(p^2)) --------------------------
__global__ void compute_y_kernel(const float* __restrict__ X, const float* __restrict__ p) {
    __shared__ float sp[F_DIM];
    __shared__ float red[8];
    int t = threadIdx.x;
    sp[t] = p[t];
    __syncthreads();
    float v = sp[t] * sp[t];
    #pragma unroll
    for (int o = 16; o; o >>= 1) v += __shfl_xor_sync(0xffffffffu, v, o);
    if ((t & 31) == 0) red[t >> 5] = v;
    __syncthreads();
    float sumsq = 0.f;
    #pragma unroll
    for (int w = 0; w < 8; ++w) sumsq += red[w];
    float inv = rsqrtf(sumsq);

    int wid = t >> 5, lane = t & 31;
    int row = blockIdx.x * 8 + wid;
    const float* xr = X + (size_t)row * F_DIM;
    float acc = 0.f;
    #pragma unroll
    for (int u = 0; u < 8; ++u) acc += xr[lane + 32 * u] * sp[lane + 32 * u];
    #pragma unroll
    for (int o = 16; o; o >>= 1) acc += __shfl_xor_sync(0xffffffffu, acc, o);
    if (lane == 0) g_y[row] = acc * inv;
}

// ---------------- 2. rank-based top-k (2 threads per node) -------------------
__global__ void rank_kernel() {
    __shared__ float sy[N_NODES];
    __shared__ int sc[256];
    int t = threadIdx.x;
    for (int j = t; j < N_NODES; j += 256) sy[j] = g_y[j];
    __syncthreads();
    int half = t >> 7;
    int i = blockIdx.x * 128 + (t & 127);
    float yi = sy[i];
    int cnt = 0;
    int j0 = half * (N_NODES / 2);
    #pragma unroll 16
    for (int jj = 0; jj < N_NODES / 2; ++jj) {
        int j = j0 + jj;
        float v = sy[j];
        cnt += (int)((v > yi) || (v == yi && j < i));
    }
    sc[t] = cnt;
    __syncthreads();
    if (half == 0) {
        int total = cnt + sc[t + 128];
        g_keep[i] = (total < K_KEEP) ? 1 : 0;
    }
}

// ---------------- 3. compact -> idx / pos ------------------------------------
__global__ void compact_kernel() {
    __shared__ int s[1024];
    int t = threadIdx.x;
    int base = t * 8;
    int flags[8];
    int c = 0;
    #pragma unroll
    for (int u = 0; u < 8; ++u) { flags[u] = g_keep[base + u]; c += flags[u]; }
    s[t] = c;
    __syncthreads();
    for (int off = 1; off < 1024; off <<= 1) {
        int add = (t >= off) ? s[t - off] : 0;
        __syncthreads();
        s[t] += add;
        __syncthreads();
    }
    int pos = s[t] - c;
    #pragma unroll
    for (int u = 0; u < 8; ++u) {
        int i = base + u;
        if (flags[u]) { g_idx[pos] = i; g_pos[i] = pos; ++pos; }
        else          { g_pos[i] = -1; }
    }
}

// ---------------- 4. X_pooled (float4, 2 per thread) -------------------------
__global__ void xpool_kernel(const float* __restrict__ X, float* __restrict__ outX) {
    int r = blockIdx.x * 8 + (threadIdx.x >> 5);
    int lane = threadIdx.x & 31;
    int i = g_idx[r];
    float g = tanhf(g_y[i]);
    const float4* src = (const float4*)(X + (size_t)i * F_DIM);
    float4* dst = (float4*)(outX + (size_t)r * F_DIM);
    #pragma unroll
    for (int u = 0; u < 2; ++u) {
        float4 v = src[lane + 32 * u];
        v.x *= g; v.y *= g; v.z *= g; v.w *= g;
        dst[lane + 32 * u] = v;
    }
}

// ---------------- 5. fused gather (float4 fill; fp16 operands) ---------------
__global__ void gather_kernel(const float* __restrict__ A) {
    __shared__ float tile[64][65];
    int R0 = blockIdx.x * 64;
    int C0 = blockIdx.y * 64;
    int t = threadIdx.x;
    #pragma unroll
    for (int i = 0; i < 4; ++i) {
        int lin = t + 256 * i;
        int r = lin >> 4, c4 = lin & 15;
        float4 v = *(const float4*)(A + (size_t)(R0 + r) * N_NODES + C0 + c4 * 4);
        tile[r][c4 * 4 + 0] = v.x;
        tile[r][c4 * 4 + 1] = v.y;
        tile[r][c4 * 4 + 2] = v.z;
        tile[r][c4 * 4 + 3] = v.w;
    }
    __syncthreads();

    int kcA = C0 >> 6;
    int kcB = R0 >> 6;
    #pragma unroll
    for (int i = 0; i < 8; ++i) {
        int lin = t + 256 * i;
        int r = lin >> 5, c2 = lin & 31;
        int p = g_pos[R0 + r];
        if (p >= 0) {
            __half2 v = __floats2half2_rn(tile[r][2 * c2], tile[r][2 * c2 + 1]);
            size_t base = (((size_t)(p >> 8)) * NKC + kcA) << 15;
            uint32_t off = swz((uint32_t)(p & 255) * 128 + c2 * 4);
            *(__half2*)(g_Atiles + base + off) = v;
        }
    }
    #pragma unroll
    for (int i = 0; i < 8; ++i) {
        int lin = t + 256 * i;
        int c = lin >> 5, r2 = lin & 31;
        int q = g_pos[C0 + c];
        if (q >= 0) {
            __half2 v = __floats2half2_rn(tile[2 * r2][c], tile[2 * r2 + 1][c]);
            size_t base = (((size_t)(q >> 8)) * NKC + kcB) << 15;
            uint32_t off = swz((uint32_t)(q & 255) * 128 + r2 * 4);
            *(__half2*)(g_Btiles + base + off) = v;
        }
    }
}

// ---------------- 6. HMMA GEMM (round-11 winner) + L2-aware rasterization ----
// BM=BN=128, BK=64, 8 warps (2x4), warp tile 64x32, 3-stage cp.async,
// one sync per k-iter, 2 CTAs/SM, f32 accumulate, streaming epilogue.
// CTA remap: 8-wide bm-major column groups -> wave working set fits L2.
__global__ void __launch_bounds__(256, 2) gemm_hmma_kernel(float* __restrict__ C) {
    extern __shared__ char smem_raw[];
    const int t = threadIdx.x;
    const int lane = t & 31, wid = t >> 5;
    const int wm = wid >> 2, wn = wid & 3;

    // L2-aware rasterization: linear id -> (bm, bn) in 8-wide bn groups, bm-major
    int lin_blk = blockIdx.y * 32 + blockIdx.x;
    int group   = lin_blk >> 8;                 // 256 CTAs per group (32 bm x 8 bn)
    int within  = lin_blk & 255;
    const int bm = within >> 3;                 // 0..31 (fast axis)
    const int bn = group * 8 + (within & 7);    // 8-wide bn band

    const char* Ag = g_Atiles + (((size_t)(bm >> 1)) * NKC) * TILE_BYTES + (size_t)(bm & 1) * 16384;
    const char* Bg = g_Btiles + (((size_t)(bn >> 1)) * NKC) * TILE_BYTES + (size_t)(bn & 1) * 16384;

    uint32_t sbase = (smem_u32(smem_raw) + 1023) & ~1023u;

    auto issue = [&](int kt) {
        uint32_t sA = sbase + (kt % STAGES) * STAGE_BYTES;
        const char* ga = Ag + (size_t)kt * TILE_BYTES;
        const char* gb = Bg + (size_t)kt * TILE_BYTES;
        #pragma unroll
        for (int i = 0; i < 4; ++i)
            cp_async16(sA + (t + 256 * i) * 16, ga + (size_t)(t + 256 * i) * 16);
        #pragma unroll
        for (int i = 0; i < 4; ++i)
            cp_async16(sA + 16384 + (t + 256 * i) * 16, gb + (size_t)(t + 256 * i) * 16);
        cp_commit();
    };

    float c[4][4][4] = {};

    issue(0); issue(1);
    for (int kt = 0; kt < NKC; ++kt) {
        if (kt < NKC - 1) asm volatile("cp.async.wait_group 1;\n" ::);
        else              asm volatile("cp.async.wait_group 0;\n" ::);
        __syncthreads();
        if (kt + 2 < NKC) issue(kt + 2);

        uint32_t sA = sbase + (kt % STAGES) * STAGE_BYTES;
        uint32_t sB = sA + 16384;
        #pragma unroll
        for (int ks = 0; ks < 4; ++ks) {
            uint32_t a[4][4], b[4][2];
            #pragma unroll
            for (int mt = 0; mt < 4; ++mt) {
                int row = wm * 64 + mt * 16 + (lane & 15);
                int chunk = (ks * 2 + (lane >> 4)) ^ (row & 7);
                ldsm4(a[mt][0], a[mt][1], a[mt][2], a[mt][3], sA + row * 128 + chunk * 16);
            }
            #pragma unroll
            for (int pr = 0; pr < 2; ++pr) {
                int row = wn * 32 + pr * 16 + ((lane >> 4) & 1) * 8 + (lane & 7);
                int chunk = (ks * 2 + ((lane >> 3) & 1)) ^ (row & 7);
                ldsm4(b[pr * 2][0], b[pr * 2][1], b[pr * 2 + 1][0], b[pr * 2 + 1][1],
                      sB + row * 128 + chunk * 16);
            }
            #pragma unroll
            for (int mt = 0; mt < 4; ++mt)
                #pragma unroll
                for (int nt = 0; nt < 4; ++nt)
                    mma16816(c[mt][nt], a[mt], b[nt]);
        }
    }
    __syncthreads();

    // epilogue: streaming stores (C is write-once)
    int groupId = lane >> 2, tid4 = lane & 3;
    #pragma unroll
    for (int mt = 0; mt < 4; ++mt) {
        size_t row0 = (size_t)bm * 128 + wm * 64 + mt * 16 + groupId;
        #pragma unroll
        for (int nt = 0; nt < 4; ++nt) {
            size_t col = (size_t)bn * 128 + wn * 32 + nt * 8 + tid4 * 2;
            __stcs((float2*)(C + row0 * K_KEEP + col),
                   make_float2(c[mt][nt][0], c[mt][nt][1]));
            __stcs((float2*)(C + (row0 + 8) * K_KEEP + col),
                   make_float2(c[mt][nt][2], c[mt][nt][3]));
        }
    }
}

// ---------------- launch ------------------------------------------------------
extern "C" void kernel_launch(void* const* d_in, const int* in_sizes, int n_in,
                              void* d_out, int out_size) {
    const float* X = (const float*)d_in[0];   // (8192, 256)
    const float* A = (const float*)d_in[1];   // (8192, 8192)
    const float* p = (const float*)d_in[2];   // (256, 1)

    float* out  = (float*)d_out;
    float* outX = out;                              // (4096, 256)
    float* outA = out + (size_t)K_KEEP * F_DIM;     // (4096, 4096)

    compute_y_kernel<<<N_NODES / 8, 256>>>(X, p);
    rank_kernel<<<N_NODES / 128, 256>>>();
    compact_kernel<<<1, 1024>>>();
    xpool_kernel<<<K_KEEP / 8, 256>>>(X, outX);
    gather_kernel<<<dim3(N_NODES / 64, N_NODES / 64), 256>>>(A);

    const int smem_bytes = STAGES * STAGE_BYTES + 1024;   // 99328 -> 2 CTAs/SM
    cudaFuncSetAttribute(gemm_hmma_kernel, cudaFuncAttributeMaxDynamicSharedMemorySize, smem_bytes);
    gemm_hmma_kernel<<<dim3(K_KEEP / 128, K_KEEP / 128), 256, smem_bytes>>>(outA);
}

// round 14
// speedup vs baseline: 1.2552x; 1.0050x over previous
#include <cuda_runtime.h>
#include <cuda_bf16.h>
#include <cstdint>

#define N_NODES 8192
#define F_DIM   256
#define K_KEEP  4096
#define KDIM    8192
#define NKC     (KDIM / 64)        // 128 k-chunks of 64 bf16
#define TILE_BYTES 32768           // 256 rows x 128 bytes (pre-swizzled)
#define STAGES  3
#define STAGE_BYTES 32768          // A 16KB + B 16KB (128 rows each)

// ---------------- scratch (__device__ globals) ------------------------------
__device__ float          g_y[N_NODES];
__device__ unsigned char  g_keep[N_NODES];
__device__ int            g_idx[K_KEEP];
__device__ int            g_pos[N_NODES];
__device__ __align__(16) char g_Atiles[(size_t)16 * NKC * TILE_BYTES];
__device__ __align__(16) char g_Btiles[(size_t)16 * NKC * TILE_BYTES];

// ---------------- PTX helpers ------------------------------------------------
__device__ __forceinline__ uint32_t smem_u32(const void* p) {
    return (uint32_t)__cvta_generic_to_shared(p);
}
__device__ __forceinline__ void cp_async16(uint32_t saddr, const void* gaddr) {
    asm volatile("cp.async.cg.shared.global [%0], [%1], 16;\n" :: "r"(saddr), "l"(gaddr));
}
__device__ __forceinline__ void cp_commit() {
    asm volatile("cp.async.commit_group;\n" ::);
}
__device__ __forceinline__ void ldsm4(uint32_t& r0, uint32_t& r1, uint32_t& r2, uint32_t& r3,
                                      uint32_t addr) {
    asm volatile("ldmatrix.sync.aligned.m8n8.x4.shared.b16 {%0,%1,%2,%3}, [%4];\n"
                 : "=r"(r0), "=r"(r1), "=r"(r2), "=r"(r3) : "r"(addr));
}
__device__ __forceinline__ void mma16816(float* c, const uint32_t* a, const uint32_t* b) {
    asm volatile("mma.sync.aligned.m16n8k16.row.col.f32.bf16.bf16.f32 "
                 "{%0,%1,%2,%3}, {%4,%5,%6,%7}, {%8,%9}, {%0,%1,%2,%3};\n"
                 : "+f"(c[0]), "+f"(c[1]), "+f"(c[2]), "+f"(c[3])
                 : "r"(a[0]), "r"(a[1]), "r"(a[2]), "r"(a[3]), "r"(b[0]), "r"(b[1]));
}
__device__ __forceinline__ void stcs16(void* gaddr, uint32_t v) {
    asm volatile("st.global.cs.b32 [%0], %1;" :: "l"(gaddr), "r"(v) : "memory");
}
__device__ __forceinline__ uint32_t swz(uint32_t off) { return off ^ ((off >> 3) & 0x70); }

// ---------------- 1. y = (X @ p) * rsqrt(sum(p^2)) --------------------------
__global__ void compute_y_kernel(const float* __restrict__ X, const float* __restrict__ p) {
    __shared__ float sp[F_DIM];
    __shared__ float red[8];
    int t = threadIdx.x;
    sp[t] = p[t];
    __syncthreads();
    float v = sp[t] * sp[t];
    #pragma unroll
    for (int o = 16; o; o >>= 1) v += __shfl_xor_sync(0xffffffffu, v, o);
    if ((t & 31) == 0) red[t >> 5] = v;
    __syncthreads();
    float sumsq = 0.f;
    #pragma unroll
    for (int w = 0; w < 8; ++w) sumsq += red[w];
    float inv = rsqrtf(sumsq);

    int wid = t >> 5, lane = t & 31;
    int row = blockIdx.x * 8 + wid;
    const float* xr = X + (size_t)row * F_DIM;
    float acc = 0.f;
    #pragma unroll
    for (int u = 0; u < 8; ++u) acc += xr[lane + 32 * u] * sp[lane + 32 * u];
    #pragma unroll
    for (int o = 16; o; o >>= 1) acc += __shfl_xor_sync(0xffffffffu, acc, o);
    if (lane == 0) g_y[row] = acc * inv;
}

// ---------------- 2. rank-based top-k (2 threads per node) -------------------
__global__ void rank_kernel() {
    __shared__ float sy[N_NODES];
    __shared__ int sc[256];
    int t = threadIdx.x;
    for (int j = t; j < N_NODES; j += 256) sy[j] = g_y[j];
    __syncthreads();
    int half = t >> 7;
    int i = blockIdx.x * 128 + (t & 127);
    float yi = sy[i];
    int cnt = 0;
    int j0 = half * (N_NODES / 2);
    #pragma unroll 16
    for (int jj = 0; jj < N_NODES / 2; ++jj) {
        int j = j0 + jj;
        float v = sy[j];
        cnt += (int)((v > yi) || (v == yi && j < i));
    }
    sc[t] = cnt;
    __syncthreads();
    if (half == 0) {
        int total = cnt + sc[t + 128];
        g_keep[i] = (total < K_KEEP) ? 1 : 0;
    }
}

// ---------------- 3. compact -> idx / pos (warp-shuffle scan) ----------------
__global__ void compact_kernel() {
    __shared__ int warp_sums[32];
    int t = threadIdx.x;
    int lane = t & 31, wid = t >> 5;
    int base = t * 8;
    int flags[8];
    int c = 0;
    #pragma unroll
    for (int u = 0; u < 8; ++u) { flags[u] = g_keep[base + u]; c += flags[u]; }
    // intra-warp inclusive scan of c
    int scan = c;
    #pragma unroll
    for (int o = 1; o < 32; o <<= 1) {
        int n = __shfl_up_sync(0xffffffffu, scan, o);
        if (lane >= o) scan += n;
    }
    if (lane == 31) warp_sums[wid] = scan;
    __syncthreads();
    if (wid == 0) {
        int s = (lane < 32) ? warp_sums[lane] : 0;
        #pragma unroll
        for (int o = 1; o < 32; o <<= 1) {
            int n = __shfl_up_sync(0xffffffffu, s, o);
            if (lane >= o) s += n;
        }
        warp_sums[lane] = s;
    }
    __syncthreads();
    int pos = scan - c + (wid ? warp_sums[wid - 1] : 0);   // exclusive prefix
    #pragma unroll
    for (int u = 0; u < 8; ++u) {
        int i = base + u;
        if (flags[u]) { g_idx[pos] = i; g_pos[i] = pos; ++pos; }
        else          { g_pos[i] = -1; }
    }
}

// ---------------- 4. X_pooled (float4, 2 per thread) -------------------------
__global__ void xpool_kernel(const float* __restrict__ X, float* __restrict__ outX) {
    int r = blockIdx.x * 8 + (threadIdx.x >> 5);
    int lane = threadIdx.x & 31;
    int i = g_idx[r];
    float g = tanhf(g_y[i]);
    const float4* src = (const float4*)(X + (size_t)i * F_DIM);
    float4* dst = (float4*)(outX + (size_t)r * F_DIM);
    #pragma unroll
    for (int u = 0; u < 2; ++u) {
        float4 v = src[lane + 32 * u];
        v.x *= g; v.y *= g; v.z *= g; v.w *= g;
        dst[lane + 32 * u] = v;
    }
}

// ---------------- 5. fused gather (float4 fill; bf16 ops; streaming writes) --
__global__ void gather_kernel(const float* __restrict__ A) {
    __shared__ float tile[64][65];
    int R0 = blockIdx.x * 64;
    int C0 = blockIdx.y * 64;
    int t = threadIdx.x;
    #pragma unroll
    for (int i = 0; i < 4; ++i) {
        int lin = t + 256 * i;
        int r = lin >> 4, c4 = lin & 15;
        float4 v = *(const float4*)(A + (size_t)(R0 + r) * N_NODES + C0 + c4 * 4);
        tile[r][c4 * 4 + 0] = v.x;
        tile[r][c4 * 4 + 1] = v.y;
        tile[r][c4 * 4 + 2] = v.z;
        tile[r][c4 * 4 + 3] = v.w;
    }
    __syncthreads();

    int kcA = C0 >> 6;
    int kcB = R0 >> 6;
    #pragma unroll
    for (int i = 0; i < 8; ++i) {
        int lin = t + 256 * i;
        int r = lin >> 5, c2 = lin & 31;
        int p = g_pos[R0 + r];
        if (p >= 0) {
            __nv_bfloat162 v = __floats2bfloat162_rn(tile[r][2 * c2], tile[r][2 * c2 + 1]);
            size_t base = (((size_t)(p >> 8)) * NKC + kcA) << 15;
            uint32_t off = swz((uint32_t)(p & 255) * 128 + c2 * 4);
            stcs16(g_Atiles + base + off, *(uint32_t*)&v);
        }
    }
    #pragma unroll
    for (int i = 0; i < 8; ++i) {
        int lin = t + 256 * i;
        int c = lin >> 5, r2 = lin & 31;
        int q = g_pos[C0 + c];
        if (q >= 0) {
            __nv_bfloat162 v = __floats2bfloat162_rn(tile[2 * r2][c], tile[2 * r2 + 1][c]);
            size_t base = (((size_t)(q >> 8)) * NKC + kcB) << 15;
            uint32_t off = swz((uint32_t)(q & 255) * 128 + r2 * 4);
            stcs16(g_Btiles + base + off, *(uint32_t*)&v);
        }
    }
}

// ---------------- 6. HMMA GEMM (round-11 champion, unchanged) ----------------
// BM=BN=128, BK=64, 8 warps (2x4), warp tile 64x32, 3-stage cp.async,
// one sync per k-iter, 2 CTAs/SM, f32 accumulate, streaming epilogue.
__global__ void __launch_bounds__(256, 2) gemm_hmma_kernel(float* __restrict__ C) {
    extern __shared__ char smem_raw[];
    const int t = threadIdx.x;
    const int lane = t & 31, wid = t >> 5;
    const int wm = wid >> 2, wn = wid & 3;
    const int bm = blockIdx.y, bn = blockIdx.x;

    const char* Ag = g_Atiles + (((size_t)(bm >> 1)) * NKC) * TILE_BYTES + (size_t)(bm & 1) * 16384;
    const char* Bg = g_Btiles + (((size_t)(bn >> 1)) * NKC) * TILE_BYTES + (size_t)(bn & 1) * 16384;

    uint32_t sbase = (smem_u32(smem_raw) + 1023) & ~1023u;

    auto issue = [&](int kt) {
        uint32_t sA = sbase + (kt % STAGES) * STAGE_BYTES;
        const char* ga = Ag + (size_t)kt * TILE_BYTES;
        const char* gb = Bg + (size_t)kt * TILE_BYTES;
        #pragma unroll
        for (int i = 0; i < 4; ++i)
            cp_async16(sA + (t + 256 * i) * 16, ga + (size_t)(t + 256 * i) * 16);
        #pragma unroll
        for (int i = 0; i < 4; ++i)
            cp_async16(sA + 16384 + (t + 256 * i) * 16, gb + (size_t)(t + 256 * i) * 16);
        cp_commit();
    };

    float c[4][4][4] = {};

    issue(0); issue(1);
    for (int kt = 0; kt < NKC; ++kt) {
        if (kt < NKC - 1) asm volatile("cp.async.wait_group 1;\n" ::);
        else              asm volatile("cp.async.wait_group 0;\n" ::);
        __syncthreads();
        if (kt + 2 < NKC) issue(kt + 2);

        uint32_t sA = sbase + (kt % STAGES) * STAGE_BYTES;
        uint32_t sB = sA + 16384;
        #pragma unroll
        for (int ks = 0; ks < 4; ++ks) {
            uint32_t a[4][4], b[4][2];
            #pragma unroll
            for (int mt = 0; mt < 4; ++mt) {
                int row = wm * 64 + mt * 16 + (lane & 15);
                int chunk = (ks * 2 + (lane >> 4)) ^ (row & 7);
                ldsm4(a[mt][0], a[mt][1], a[mt][2], a[mt][3], sA + row * 128 + chunk * 16);
            }
            #pragma unroll
            for (int pr = 0; pr < 2; ++pr) {
                int row = wn * 32 + pr * 16 + ((lane >> 4) & 1) * 8 + (lane & 7);
                int chunk = (ks * 2 + ((lane >> 3) & 1)) ^ (row & 7);
                ldsm4(b[pr * 2][0], b[pr * 2][1], b[pr * 2 + 1][0], b[pr * 2 + 1][1],
                      sB + row * 128 + chunk * 16);
            }
            #pragma unroll
            for (int mt = 0; mt < 4; ++mt)
                #pragma unroll
                for (int nt = 0; nt < 4; ++nt)
                    mma16816(c[mt][nt], a[mt], b[nt]);
        }
    }
    __syncthreads();

    // epilogue: streaming stores (C is write-once)
    int groupId = lane >> 2, tid4 = lane & 3;
    #pragma unroll
    for (int mt = 0; mt < 4; ++mt) {
        size_t row0 = (size_t)bm * 128 + wm * 64 + mt * 16 + groupId;
        #pragma unroll
        for (int nt = 0; nt < 4; ++nt) {
            size_t col = (size_t)bn * 128 + wn * 32 + nt * 8 + tid4 * 2;
            __stcs((float2*)(C + row0 * K_KEEP + col),
                   make_float2(c[mt][nt][0], c[mt][nt][1]));
            __stcs((float2*)(C + (row0 + 8) * K_KEEP + col),
                   make_float2(c[mt][nt][2], c[mt][nt][3]));
        }
    }
}

// ---------------- launch ------------------------------------------------------
extern "C" void kernel_launch(void* const* d_in, const int* in_sizes, int n_in,
                              void* d_out, int out_size) {
    const float* X = (const float*)d_in[0];   // (8192, 256)
    const float* A = (const float*)d_in[1];   // (8192, 8192)
    const float* p = (const float*)d_in[2];   // (256, 1)

    float* out  = (float*)d_out;
    float* outX = out;                              // (4096, 256)
    float* outA = out + (size_t)K_KEEP * F_DIM;     // (4096, 4096)

    compute_y_kernel<<<N_NODES / 8, 256>>>(X, p);
    rank_kernel<<<N_NODES / 128, 256>>>();
    compact_kernel<<<1, 1024>>>();
    xpool_kernel<<<K_KEEP / 8, 256>>>(X, outX);
    gather_kernel<<<dim3(N_NODES / 64, N_NODES / 64), 256>>>(A);

    const int smem_bytes = STAGES * STAGE_BYTES + 1024;   // 99328 -> 2 CTAs/SM
    cudaFuncSetAttribute(gemm_hmma_kernel, cudaFuncAttributeMaxDynamicSharedMemorySize, smem_bytes);
    gemm_hmma_kernel<<<dim3(K_KEEP / 128, K_KEEP / 128), 256, smem_bytes>>>(outA);
}